// round 1
// baseline (speedup 1.0000x reference)
#include <cuda_runtime.h>
#include <math.h>

#define Bn 64
#define Hn 512
#define En 256
#define Vn 32000
#define Sn 64
#define NVB 500   /* Vn / 64 v-blocks in logits kernel */

// ---------------- persistent device state (no cudaMalloc allowed) ------------
__device__ float g_h[2][Bn * Hn];        // double-buffered hidden state
__device__ float g_c[Bn * Hn];           // cell state (owned per (b,j), single buffer)
__device__ float g_gates[4 * Hn * Bn];   // gate accumulator, layout [row][b]
__device__ float g_pval[Bn * NVB];       // argmax partials (value)
__device__ int   g_pidx[Bn * NVB];       // argmax partials (index)
__device__ int   g_tf[Sn];               // decoded use_tf flags

__device__ __forceinline__ float sigmoidf_(float x) {
    return 1.0f / (1.0f + expf(-x));
}

// ---------------- init: decode use_tf layout, zero scratch + out[:,0,:] ------
__global__ void init_kernel(const unsigned char* tf_raw, float* out) {
    if (blockIdx.x == 0) {
        __shared__ int mode;  // 0 = 1-byte bool, 1 = 4-byte word (int32/float32)
        if (threadIdx.x == 0) {
            int gt1 = 0, odd1 = 0;
            for (int i = 0; i < Sn; i++) {
                unsigned char v = tf_raw[i];
                if (v > 1) gt1 = 1;              // float32 pattern bytes (0x80/0x3f)
                if (v == 1 && (i & 3)) odd1 = 1; // byte layout: 1s at non-mult-4 pos
            }
            mode = gt1 ? 1 : (odd1 ? 0 : 1);
        }
        __syncthreads();
        if (threadIdx.x < Sn) {
            int t = threadIdx.x;
            int val;
            if (mode == 0) val = (tf_raw[t] != 0);
            else           val = (((const unsigned int*)tf_raw)[t] != 0u);
            g_tf[t] = val;
        }
    }
    // zero gate accumulator
    for (int i = blockIdx.x * blockDim.x + threadIdx.x; i < 4 * Hn * Bn;
         i += gridDim.x * blockDim.x)
        g_gates[i] = 0.0f;
    // zero out[:, 0, :]
    for (int i = blockIdx.x * blockDim.x + threadIdx.x; i < Bn * Vn;
         i += gridDim.x * blockDim.x) {
        int b = i / Vn, v = i - b * Vn;
        out[(size_t)b * Sn * Vn + v] = 0.0f;
    }
}

// ---------------- gates: split-K GEMM with atomic accumulation ---------------
// grid (16 j-blocks, 6 k-slices) x 256 threads.
// slices 0..1: x-part (k 0..255 of concat), slices 2..5: h-part (k 0..511).
// Each block: 128 W-rows (= 4 gates x 32 j) x 64 batches x 128 k.
__global__ __launch_bounds__(256) void gates_kernel(
    int k, const int* __restrict__ captions, const float* __restrict__ emb,
    const float* __restrict__ W_ih, const float* __restrict__ W_hh,
    const float* __restrict__ enc)
{
    __shared__ float xh_s[32][68];   // [kk][b]
    __shared__ float w_s[32][132];   // [kk][row]
    __shared__ int   tok_s[Bn];

    int tid = threadIdx.x;
    int j0 = blockIdx.x * 32;
    int slice = blockIdx.y;
    bool xpart = (slice < 2);
    int kslice0 = xpart ? slice * 128 : (slice - 2) * 128;

    // resolve tokens (only x-slices need the embedding row index)
    if (xpart) {
        if (k == 0) {
            if (tid < Bn) tok_s[tid] = captions[tid * Sn + 0];
        } else {
            int b = tid >> 2, l4 = tid & 3;
            float bv = -3.4e38f; int bi = 0x7fffffff;
            for (int p = l4; p < NVB; p += 4) {
                float v = g_pval[b * NVB + p];
                int  ii = g_pidx[b * NVB + p];
                if (v > bv || (v == bv && ii < bi)) { bv = v; bi = ii; }
            }
            #pragma unroll
            for (int off = 2; off > 0; off >>= 1) {
                float ov = __shfl_down_sync(0xffffffffu, bv, off, 4);
                int   oi = __shfl_down_sync(0xffffffffu, bi, off, 4);
                if (ov > bv || (ov == bv && oi < bi)) { bv = ov; bi = oi; }
            }
            if (l4 == 0)
                tok_s[b] = g_tf[k] ? captions[b * Sn + k] : bi;
        }
    }
    __syncthreads();

    float acc[4][8];
    #pragma unroll
    for (int g = 0; g < 4; g++)
        #pragma unroll
        for (int u = 0; u < 8; u++) acc[g][u] = 0.0f;

    int jj = tid & 31, bb = tid >> 5;

    for (int t8 = 0; t8 < 4; t8++) {
        int kb = t8 * 32;
        // fill xh tile (64 b x 32 k)
        {
            int b = tid >> 2, kq = tid & 3;
            int kk0 = kq * 8;
            if (xpart) {
                int tok = tok_s[b];
                const float* row = emb + (size_t)tok * En;
                #pragma unroll
                for (int i = 0; i < 8; i++) {
                    int kg = kslice0 + kb + kk0 + i;
                    xh_s[kk0 + i][b] = (tok == 0) ? 0.0f : row[kg];
                }
            } else {
                const float* hsrc = (k == 0) ? (enc + b * Hn) : (&g_h[k & 1][b * Hn]);
                #pragma unroll
                for (int i = 0; i < 8; i++) {
                    int kg = kslice0 + kb + kk0 + i;
                    xh_s[kk0 + i][b] = hsrc[kg];
                }
            }
        }
        // fill W tile (128 rows x 32 k), transposed to [kk][row]
        {
            int k4 = tid & 7, r0 = tid >> 3;
            #pragma unroll
            for (int pass = 0; pass < 4; pass++) {
                int r = r0 + pass * 32;
                int gate = r >> 5;
                int R = gate * Hn + j0 + (r & 31);
                int kg = kslice0 + kb + k4 * 4;
                const float* wptr = xpart ? (W_ih + (size_t)R * En + kg)
                                          : (W_hh + (size_t)R * Hn + kg);
                float4 w4 = *(const float4*)wptr;
                w_s[k4 * 4 + 0][r] = w4.x;
                w_s[k4 * 4 + 1][r] = w4.y;
                w_s[k4 * 4 + 2][r] = w4.z;
                w_s[k4 * 4 + 3][r] = w4.w;
            }
        }
        __syncthreads();
        #pragma unroll
        for (int kk = 0; kk < 32; kk++) {
            float w0 = w_s[kk][jj], w1 = w_s[kk][32 + jj];
            float w2 = w_s[kk][64 + jj], w3 = w_s[kk][96 + jj];
            float4 hA = *(const float4*)&xh_s[kk][bb * 8];
            float4 hB = *(const float4*)&xh_s[kk][bb * 8 + 4];
            float hv[8] = {hA.x, hA.y, hA.z, hA.w, hB.x, hB.y, hB.z, hB.w};
            #pragma unroll
            for (int u = 0; u < 8; u++) {
                acc[0][u] += w0 * hv[u];
                acc[1][u] += w1 * hv[u];
                acc[2][u] += w2 * hv[u];
                acc[3][u] += w3 * hv[u];
            }
        }
        __syncthreads();
    }

    #pragma unroll
    for (int g = 0; g < 4; g++) {
        int R = g * Hn + j0 + jj;
        #pragma unroll
        for (int u = 0; u < 8; u++)
            atomicAdd(&g_gates[R * Bn + bb * 8 + u], acc[g][u]);
    }
}

// ---------------- cell update; also re-zeros gate accumulator ----------------
__global__ __launch_bounds__(256) void cell_kernel(
    int k, const float* __restrict__ b_ih, const float* __restrict__ b_hh)
{
    int idx = blockIdx.x * 256 + threadIdx.x;  // 0..32767
    int b = idx & 63;
    int j = idx >> 6;

    float gi = g_gates[(0 * Hn + j) * Bn + b] + b_ih[0 * Hn + j] + b_hh[0 * Hn + j];
    float gf = g_gates[(1 * Hn + j) * Bn + b] + b_ih[1 * Hn + j] + b_hh[1 * Hn + j];
    float gg = g_gates[(2 * Hn + j) * Bn + b] + b_ih[2 * Hn + j] + b_hh[2 * Hn + j];
    float go = g_gates[(3 * Hn + j) * Bn + b] + b_ih[3 * Hn + j] + b_hh[3 * Hn + j];

    float c_old = (k == 0) ? 0.0f : g_c[b * Hn + j];
    float c = sigmoidf_(gf) * c_old + sigmoidf_(gi) * tanhf(gg);
    float h = sigmoidf_(go) * tanhf(c);
    g_c[b * Hn + j] = c;
    g_h[(k + 1) & 1][b * Hn + j] = h;

    g_gates[(0 * Hn + j) * Bn + b] = 0.0f;
    g_gates[(1 * Hn + j) * Bn + b] = 0.0f;
    g_gates[(2 * Hn + j) * Bn + b] = 0.0f;
    g_gates[(3 * Hn + j) * Bn + b] = 0.0f;
}

// ---------------- logits GEMM + argmax partials ------------------------------
// grid 500 x 256 threads. Block tile: 64 v x 64 b, thread tile 4v x 4b.
__global__ __launch_bounds__(256) void logits_kernel(
    int k, const float* __restrict__ fc_w, const float* __restrict__ fc_b,
    float* __restrict__ out)
{
    __shared__ float w_s[32][68];  // [kk][v]
    __shared__ float h_s[32][68];  // [kk][b]
    int tid = threadIdx.x;
    int v0 = blockIdx.x * 64;
    int tv = tid & 15, tb = tid >> 4;
    const float* hcur = g_h[(k + 1) & 1];

    float acc[4][4];
    #pragma unroll
    for (int i = 0; i < 4; i++)
        #pragma unroll
        for (int j = 0; j < 4; j++) acc[i][j] = 0.0f;

    for (int t8 = 0; t8 < 16; t8++) {
        int kb = t8 * 32;
        {
            int k4 = tid & 7, vv0 = tid >> 3;
            #pragma unroll
            for (int pass = 0; pass < 2; pass++) {
                int vv = vv0 + pass * 32;
                float4 w4 = *(const float4*)(fc_w + (size_t)(v0 + vv) * Hn + kb + k4 * 4);
                w_s[k4 * 4 + 0][vv] = w4.x;
                w_s[k4 * 4 + 1][vv] = w4.y;
                w_s[k4 * 4 + 2][vv] = w4.z;
                w_s[k4 * 4 + 3][vv] = w4.w;
            }
        }
        {
            int b = tid >> 2, kq = tid & 3;
            float4 a = *(const float4*)(hcur + b * Hn + kb + kq * 8);
            float4 c = *(const float4*)(hcur + b * Hn + kb + kq * 8 + 4);
            h_s[kq * 8 + 0][b] = a.x; h_s[kq * 8 + 1][b] = a.y;
            h_s[kq * 8 + 2][b] = a.z; h_s[kq * 8 + 3][b] = a.w;
            h_s[kq * 8 + 4][b] = c.x; h_s[kq * 8 + 5][b] = c.y;
            h_s[kq * 8 + 6][b] = c.z; h_s[kq * 8 + 7][b] = c.w;
        }
        __syncthreads();
        #pragma unroll
        for (int kk = 0; kk < 32; kk++) {
            float4 w = *(const float4*)&w_s[kk][tv * 4];
            float4 h = *(const float4*)&h_s[kk][tb * 4];
            float wv[4] = {w.x, w.y, w.z, w.w};
            float hv[4] = {h.x, h.y, h.z, h.w};
            #pragma unroll
            for (int i = 0; i < 4; i++)
                #pragma unroll
                for (int j = 0; j < 4; j++)
                    acc[i][j] += wv[i] * hv[j];
        }
        __syncthreads();
    }

    int t = k + 1;
    float bias[4];
    #pragma unroll
    for (int i = 0; i < 4; i++) bias[i] = fc_b[v0 + tv * 4 + i];

    #pragma unroll
    for (int j = 0; j < 4; j++) {
        int b = tb * 4 + j;
        float vals[4];
        #pragma unroll
        for (int i = 0; i < 4; i++) vals[i] = acc[i][j] + bias[i];

        float4 r = make_float4(vals[0], vals[1], vals[2], vals[3]);
        *(float4*)(out + ((size_t)b * Sn + t) * Vn + v0 + tv * 4) = r;

        // per-b argmax partial over this block's 64 v (lowest index on ties)
        float bv = vals[0]; int bi = v0 + tv * 4;
        #pragma unroll
        for (int i = 1; i < 4; i++)
            if (vals[i] > bv) { bv = vals[i]; bi = v0 + tv * 4 + i; }
        #pragma unroll
        for (int off = 8; off > 0; off >>= 1) {
            float ov = __shfl_down_sync(0xffffffffu, bv, off, 16);
            int   oi = __shfl_down_sync(0xffffffffu, bi, off, 16);
            if (ov > bv || (ov == bv && oi < bi)) { bv = ov; bi = oi; }
        }
        if (tv == 0) {
            g_pval[b * NVB + blockIdx.x] = bv;
            g_pidx[b * NVB + blockIdx.x] = bi;
        }
    }
}

// ---------------- launch ------------------------------------------------------
extern "C" void kernel_launch(void* const* d_in, const int* in_sizes, int n_in,
                              void* d_out, int out_size) {
    (void)in_sizes; (void)n_in; (void)out_size;
    const float*         enc  = (const float*)d_in[0];
    const int*           caps = (const int*)d_in[1];
    const unsigned char* tf   = (const unsigned char*)d_in[2];
    const float*         emb  = (const float*)d_in[3];
    const float*         W_ih = (const float*)d_in[4];
    const float*         W_hh = (const float*)d_in[5];
    const float*         b_ih = (const float*)d_in[6];
    const float*         b_hh = (const float*)d_in[7];
    const float*         fc_w = (const float*)d_in[8];
    const float*         fc_b = (const float*)d_in[9];
    float* out = (float*)d_out;

    init_kernel<<<512, 256>>>(tf, out);
    dim3 gGrid(16, 6);
    for (int k = 0; k < 63; k++) {
        gates_kernel<<<gGrid, 256>>>(k, caps, emb, W_ih, W_hh, enc);
        cell_kernel<<<128, 256>>>(k, b_ih, b_hh);
        logits_kernel<<<500, 256>>>(k, fc_w, fc_b, out);
    }
}